// round 3
// baseline (speedup 1.0000x reference)
#include <cuda_runtime.h>
#include <cstdint>

// ============================================================
// QDotGeneral — AQT-style symmetric int8 quantized dot_general
//   lhs [4,8192,1024] f32  -> per-row (over K) scale
//   rhs [1024,1024]  f32   -> per-col (over K) scale
//   out [4,8192,1024] f32 = (q_l . q_r) * s_l * s_r
//
// Harness compiles for baseline sm_100 (no 'a' features) -> tcgen05 is
// unavailable; use classic mma.sync m16n8k32 s8 IMMA path: exact int32
// accumulation, identical to the reference's integer GEMM.
// ============================================================

#define M_TOTAL 32768
#define K_DIM   1024
#define N_DIM   1024

// Scratch (device globals — allocations are forbidden)
__device__ int8_t g_qA[(size_t)M_TOTAL * K_DIM];   // [M,K] s8
__device__ float  g_sA[M_TOTAL];
__device__ int8_t g_qB[(size_t)N_DIM * K_DIM];     // [N,K] s8 (rhs transposed)
__device__ float  g_sB[N_DIM];

// ---------------- PTX helpers (baseline-arch only) ----------------
__device__ __forceinline__ uint32_t smem_u32(const void* p) {
    return (uint32_t)__cvta_generic_to_shared(p);
}
__device__ __forceinline__ void cp16(uint32_t s, const void* g) {
    size_t ga = __cvta_generic_to_global(g);
    asm volatile("cp.async.cg.shared.global [%0], [%1], 16;" :: "r"(s), "l"(ga) : "memory");
}
__device__ __forceinline__ void cp_commit() {
    asm volatile("cp.async.commit_group;" ::: "memory");
}
template <int N>
__device__ __forceinline__ void cp_wait() {
    asm volatile("cp.async.wait_group %0;" :: "n"(N) : "memory");
}
__device__ __forceinline__ void ldsm_x4(uint32_t& r0, uint32_t& r1, uint32_t& r2,
                                        uint32_t& r3, uint32_t addr) {
    asm volatile("ldmatrix.sync.aligned.m8n8.x4.shared.b16 {%0,%1,%2,%3}, [%4];"
                 : "=r"(r0), "=r"(r1), "=r"(r2), "=r"(r3) : "r"(addr));
}
__device__ __forceinline__ void mma_s8(int32_t* c, const uint32_t* a, const uint32_t* b) {
    asm volatile(
        "mma.sync.aligned.m16n8k32.row.col.s32.s8.s8.s32 "
        "{%0,%1,%2,%3}, {%4,%5,%6,%7}, {%8,%9}, {%0,%1,%2,%3};"
        : "+r"(c[0]), "+r"(c[1]), "+r"(c[2]), "+r"(c[3])
        : "r"(a[0]), "r"(a[1]), "r"(a[2]), "r"(a[3]), "r"(b[0]), "r"(b[1]));
}

// ---------------- Quantization kernels ----------------

// rhs [K=1024, N=1024] f32: per-column absmax over K; write q_r^T [N,K] s8.
__global__ void __launch_bounds__(256) quant_rhs_kernel(const float* __restrict__ rhs) {
    int lane = threadIdx.x & 31;
    int w = threadIdx.x >> 5;           // 8 warps
    int n = blockIdx.x * 32 + lane;     // 32 columns per block

    float m = 0.0f;
    for (int k = w; k < K_DIM; k += 8)
        m = fmaxf(m, fabsf(rhs[(size_t)k * N_DIM + n]));

    __shared__ float red[8][32];
    __shared__ float s_sh[32];
    red[w][lane] = m;
    __syncthreads();
    if (w == 0) {
        float mm = red[0][lane];
        #pragma unroll
        for (int i = 1; i < 8; i++) mm = fmaxf(mm, red[i][lane]);
        float s = mm / 127.0f;
        if (s == 0.0f) s = 1.0f;
        g_sB[n] = s;
        s_sh[lane] = s;
    }
    __syncthreads();
    float s = s_sh[lane];
    for (int k = w; k < K_DIM; k += 8) {
        float q = fminf(fmaxf(rintf(rhs[(size_t)k * N_DIM + n] / s), -127.0f), 127.0f);
        g_qB[(size_t)n * K_DIM + k] = (int8_t)(int)q;
    }
}

// lhs [M, K=1024] f32 row-major: per-row absmax; write q_l [M,K] s8.
__global__ void __launch_bounds__(256) quant_lhs_kernel(const float* __restrict__ lhs) {
    int row = blockIdx.x;
    const float4* p = reinterpret_cast<const float4*>(lhs) + (size_t)row * 256;
    float4 v = p[threadIdx.x];
    float m = fmaxf(fmaxf(fabsf(v.x), fabsf(v.y)), fmaxf(fabsf(v.z), fabsf(v.w)));
    #pragma unroll
    for (int o = 16; o > 0; o >>= 1)
        m = fmaxf(m, __shfl_xor_sync(0xffffffffu, m, o));

    __shared__ float wmax[8];
    __shared__ float s_bcast;
    if ((threadIdx.x & 31) == 0) wmax[threadIdx.x >> 5] = m;
    __syncthreads();
    if (threadIdx.x == 0) {
        float mm = wmax[0];
        #pragma unroll
        for (int i = 1; i < 8; i++) mm = fmaxf(mm, wmax[i]);
        float s = mm / 127.0f;
        if (s == 0.0f) s = 1.0f;
        g_sA[row] = s;
        s_bcast = s;
    }
    __syncthreads();
    float s = s_bcast;
    char4 q;
    q.x = (char)(int)fminf(fmaxf(rintf(v.x / s), -127.0f), 127.0f);
    q.y = (char)(int)fminf(fmaxf(rintf(v.y / s), -127.0f), 127.0f);
    q.z = (char)(int)fminf(fmaxf(rintf(v.z / s), -127.0f), 127.0f);
    q.w = (char)(int)fminf(fmaxf(rintf(v.w / s), -127.0f), 127.0f);
    reinterpret_cast<char4*>(g_qA)[(size_t)row * 256 + threadIdx.x] = q;
}

// ---------------- GEMM kernel (int8 mma.sync) ----------------
// CTA 128x128, BK=128 (s8 -> 128B rows, SW128 XOR swizzle), 256 thr,
// 8 warps (2 M x 4 N), warp tile 64x32, 2-stage cp.async double buffer.

#define BM 128
#define BN 128
#define BK 128
#define NKB (K_DIM / BK)                // 8
#define STAGE_A 16384                   // 128 * 128 bytes
#define STAGE_B 16384
#define SMEM_TOTAL (2 * STAGE_A + 2 * STAGE_B)   // 65536

__global__ void __launch_bounds__(256, 2)
gemm_s8_kernel(float* __restrict__ out) {
    extern __shared__ __align__(1024) char smem[];
    uint32_t sbase = smem_u32(smem);
    int tid = threadIdx.x;
    int wid = tid >> 5;
    int lid = tid & 31;
    int warpm = wid & 1;        // 0..1 -> 64-row slab
    int warpn = wid >> 1;       // 0..3 -> 32-col slab
    int m0 = blockIdx.x * BM;
    int n0 = blockIdx.y * BN;

    uint32_t sA[2] = { sbase, sbase + STAGE_A };
    uint32_t sB[2] = { sbase + 2 * STAGE_A, sbase + 2 * STAGE_A + STAGE_B };

    const int8_t* gA = g_qA + (size_t)m0 * K_DIM;
    const int8_t* gB = g_qB + (size_t)n0 * K_DIM;

    // cp.async chunk mapping: chunk = tid + 256*i; r = chunk>>3, c = chunk&7
    // swizzled smem offset: r*128 + ((c ^ (r&7)) << 4)
    auto load_stage = [&](int st, int kb) {
        #pragma unroll
        for (int i = 0; i < 4; i++) {
            int chunk = tid + 256 * i;
            int r = chunk >> 3, c = chunk & 7;
            uint32_t off = (uint32_t)(r * 128 + ((c ^ (r & 7)) << 4));
            cp16(sA[st] + off, gA + (size_t)r * K_DIM + kb * BK + c * 16);
        }
        #pragma unroll
        for (int i = 0; i < 4; i++) {
            int chunk = tid + 256 * i;
            int r = chunk >> 3, c = chunk & 7;
            uint32_t off = (uint32_t)(r * 128 + ((c ^ (r & 7)) << 4));
            cp16(sB[st] + off, gB + (size_t)r * K_DIM + kb * BK + c * 16);
        }
        cp_commit();
    };

    // ldmatrix lane->matrix mapping for mma.m16n8k32:
    //
    // A fragment needs matrices (rows0-7/k0-15, rows8-15/k0-15,
    //                            rows0-7/k16-31, rows8-15/k16-31):
    //   lanes 0-15  -> rows 0-15, first 16B chunk of the 32B k-step
    //   lanes 16-31 -> rows 0-15, second 16B chunk
    int lrowA = lid & 15;
    int halfA = lid >> 4;
    //
    // B fragment needs matrices (n0-7/k0-15, n0-7/k16-31,
    //                            n8-15/k0-15, n8-15/k16-31):
    //   lanes 0-7: n0-7 chunk0; 8-15: n0-7 chunk1; 16-23: n8-15 chunk0; ...
    int lrowB = ((lid >> 4) << 3) + (lid & 7);
    int halfB = (lid >> 3) & 1;
    //
    // Swizzle phase = (absolute row & 7); all row bases are multiples of 8,
    // and (lrowA&7) == (lrowB&7) == (lid&7).
    int phase = lid & 7;

    uint32_t aRow0 = (uint32_t)((warpm * 64 + lrowA) * 128);
    uint32_t bRow0 = (uint32_t)((warpn * 32 + lrowB) * 128);

    int32_t acc[4][4][4];
    #pragma unroll
    for (int mt = 0; mt < 4; mt++)
        #pragma unroll
        for (int nt = 0; nt < 4; nt++)
            #pragma unroll
            for (int i = 0; i < 4; i++) acc[mt][nt][i] = 0;

    load_stage(0, 0);
    load_stage(1, 1);

    for (int kb = 0; kb < NKB; kb++) {
        int st = kb & 1;
        if (kb == NKB - 1) cp_wait<0>(); else cp_wait<1>();
        __syncthreads();

        #pragma unroll
        for (int ks = 0; ks < 4; ks++) {
            uint32_t aChunk = (uint32_t)(((2 * ks + halfA) ^ phase) << 4);
            uint32_t bChunk = (uint32_t)(((2 * ks + halfB) ^ phase) << 4);
            uint32_t a[4][4], b[4][2];
            #pragma unroll
            for (int mt = 0; mt < 4; mt++) {
                uint32_t addr = sA[st] + aRow0 + (uint32_t)(mt * 16 * 128) + aChunk;
                ldsm_x4(a[mt][0], a[mt][1], a[mt][2], a[mt][3], addr);
            }
            #pragma unroll
            for (int np = 0; np < 2; np++) {
                uint32_t addr = sB[st] + bRow0 + (uint32_t)(np * 16 * 128) + bChunk;
                ldsm_x4(b[2 * np][0], b[2 * np][1], b[2 * np + 1][0], b[2 * np + 1][1], addr);
            }
            #pragma unroll
            for (int mt = 0; mt < 4; mt++)
                #pragma unroll
                for (int nt = 0; nt < 4; nt++)
                    mma_s8(acc[mt][nt], a[mt], b[nt]);
        }

        __syncthreads();
        if (kb + 2 < NKB) load_stage(st, kb + 2);
    }

    // Epilogue: dequantize and store. Thread holds rows g,g+8 cols 2*tig,+1
    int g = lid >> 2, tig = lid & 3;
    #pragma unroll
    for (int mt = 0; mt < 4; mt++) {
        int mA = m0 + warpm * 64 + mt * 16 + g;
        float slA = g_sA[mA];
        float slB = g_sA[mA + 8];
        float* rowA = out + (size_t)mA * N_DIM + n0 + warpn * 32;
        float* rowB = rowA + 8 * N_DIM;
        #pragma unroll
        for (int nt = 0; nt < 4; nt++) {
            int n = nt * 8 + 2 * tig;
            float2 sr = *reinterpret_cast<const float2*>(&g_sB[n0 + warpn * 32 + n]);
            float2 vA, vB;
            vA.x = __int2float_rn(acc[mt][nt][0]) * slA * sr.x;
            vA.y = __int2float_rn(acc[mt][nt][1]) * slA * sr.y;
            vB.x = __int2float_rn(acc[mt][nt][2]) * slB * sr.x;
            vB.y = __int2float_rn(acc[mt][nt][3]) * slB * sr.y;
            *reinterpret_cast<float2*>(rowA + n) = vA;
            *reinterpret_cast<float2*>(rowB + n) = vB;
        }
    }
}

// ---------------- Launch ----------------
extern "C" void kernel_launch(void* const* d_in, const int* in_sizes, int n_in,
                              void* d_out, int out_size) {
    const float* lhs = (const float*)d_in[0];   // [32768, 1024] f32
    const float* rhs = (const float*)d_in[1];   // [1024, 1024] f32
    float* out = (float*)d_out;                 // [32768, 1024] f32

    int M = in_sizes[0] / K_DIM;                // 32768

    cudaFuncSetAttribute(gemm_s8_kernel,
                         cudaFuncAttributeMaxDynamicSharedMemorySize, SMEM_TOTAL);

    quant_rhs_kernel<<<N_DIM / 32, 256>>>(rhs);
    quant_lhs_kernel<<<M, 256>>>(lhs);

    dim3 grid(M / BM, N_DIM / BN);              // (256, 8)
    gemm_s8_kernel<<<grid, 256, SMEM_TOTAL>>>(out);
}

// round 4
// speedup vs baseline: 1.1780x; 1.1780x over previous
#include <cuda_runtime.h>
#include <cstdint>

// ============================================================
// QDotGeneral — AQT-style symmetric int8 quantized dot_general
//   lhs [4,8192,1024] f32  -> per-row (over K) scale
//   rhs [1024,1024]  f32   -> per-col (over K) scale
//   out [4,8192,1024] f32 = (q_l . q_r) * s_l * s_r
//
// Baseline sm_100 target (no 'a' features) -> classic mma.sync
// m16n8k32 s8 IMMA path: exact int32 accumulation.
// ============================================================

#define M_TOTAL 32768
#define K_DIM   1024
#define N_DIM   1024

// Scratch (device globals — allocations are forbidden)
__device__ int8_t g_qA[(size_t)M_TOTAL * K_DIM];   // [M,K] s8
__device__ float  g_sA[M_TOTAL];
__device__ int8_t g_qB[(size_t)N_DIM * K_DIM];     // [N,K] s8 (rhs transposed)
__device__ float  g_sB[N_DIM];
__device__ float  g_pmax[16][N_DIM];               // rhs partial col-max

// ---------------- PTX helpers (baseline-arch only) ----------------
__device__ __forceinline__ uint32_t smem_u32(const void* p) {
    return (uint32_t)__cvta_generic_to_shared(p);
}
__device__ __forceinline__ void cp16(uint32_t s, const void* g) {
    size_t ga = __cvta_generic_to_global(g);
    asm volatile("cp.async.cg.shared.global [%0], [%1], 16;" :: "r"(s), "l"(ga) : "memory");
}
__device__ __forceinline__ void cp_commit() {
    asm volatile("cp.async.commit_group;" ::: "memory");
}
template <int N>
__device__ __forceinline__ void cp_wait() {
    asm volatile("cp.async.wait_group %0;" :: "n"(N) : "memory");
}
__device__ __forceinline__ void ldsm_x4(uint32_t& r0, uint32_t& r1, uint32_t& r2,
                                        uint32_t& r3, uint32_t addr) {
    asm volatile("ldmatrix.sync.aligned.m8n8.x4.shared.b16 {%0,%1,%2,%3}, [%4];"
                 : "=r"(r0), "=r"(r1), "=r"(r2), "=r"(r3) : "r"(addr));
}
__device__ __forceinline__ void mma_s8(int32_t* c, const uint32_t* a, const uint32_t* b) {
    asm volatile(
        "mma.sync.aligned.m16n8k32.row.col.s32.s8.s8.s32 "
        "{%0,%1,%2,%3}, {%4,%5,%6,%7}, {%8,%9}, {%0,%1,%2,%3};"
        : "+r"(c[0]), "+r"(c[1]), "+r"(c[2]), "+r"(c[3])
        : "r"(a[0]), "r"(a[1]), "r"(a[2]), "r"(a[3]), "r"(b[0]), "r"(b[1]));
}

// ---------------- RHS quantization (2 wide kernels) ----------------

// Pass 1: partial column-absmax. grid (8, 16), 256 thr.
// Block (bx,by): cols bx*128..+127, k-rows by*64..+63.
__global__ void __launch_bounds__(256) rhs_pmax_kernel(const float* __restrict__ rhs) {
    int col = blockIdx.x * 128 + (threadIdx.x & 127);
    int rh = threadIdx.x >> 7;               // 0/1
    int k0 = blockIdx.y * 64;
    float m = 0.0f;
    #pragma unroll 4
    for (int r = rh; r < 64; r += 2)
        m = fmaxf(m, fabsf(rhs[(size_t)(k0 + r) * N_DIM + col]));
    __shared__ float red[256];
    red[threadIdx.x] = m;
    __syncthreads();
    if (rh == 0)
        g_pmax[blockIdx.y][col] = fmaxf(red[threadIdx.x], red[threadIdx.x + 128]);
}

// Pass 2: reduce partials -> scale, quantize + transpose to [N,K].
// grid (8, 16), 256 thr. smem tile stride 80 (16-aligned rows).
__global__ void __launch_bounds__(256) quant_rhs2_kernel(const float* __restrict__ rhs) {
    __shared__ float sc[128];
    __shared__ __align__(16) int8_t qt[128][80];
    int n0 = blockIdx.x * 128, k0 = blockIdx.y * 64;
    int t = threadIdx.x;

    if (t < 128) {
        float m = 0.0f;
        #pragma unroll
        for (int i = 0; i < 16; i++) m = fmaxf(m, g_pmax[i][n0 + t]);
        float s = m / 127.0f;
        if (s == 0.0f) s = 1.0f;
        sc[t] = s;
        if (blockIdx.y == 0) g_sB[n0 + t] = s;
    }
    __syncthreads();

    int col = t & 127, rh = t >> 7;
    float s = sc[col];
    #pragma unroll 4
    for (int r = rh; r < 64; r += 2) {
        float v = rhs[(size_t)(k0 + r) * N_DIM + n0 + col];
        float q = fminf(fmaxf(rintf(v / s), -127.0f), 127.0f);
        qt[col][r] = (int8_t)(int)q;
    }
    __syncthreads();

    // write transpose: 128 cols (now rows of q_r^T) x 64B, int4 chunks
    #pragma unroll
    for (int i = t; i < 512; i += 256) {
        int n = i >> 2, c = i & 3;
        *reinterpret_cast<int4*>(&g_qB[(size_t)(n0 + n) * K_DIM + k0 + c * 16]) =
            *reinterpret_cast<const int4*>(&qt[n][c * 16]);
    }
}

// ---------------- LHS quantization ----------------
// lhs [M, K=1024] f32 row-major: per-row absmax; write q_l [M,K] s8.
__global__ void __launch_bounds__(256) quant_lhs_kernel(const float* __restrict__ lhs) {
    int row = blockIdx.x;
    const float4* p = reinterpret_cast<const float4*>(lhs) + (size_t)row * 256;
    float4 v = p[threadIdx.x];
    float m = fmaxf(fmaxf(fabsf(v.x), fabsf(v.y)), fmaxf(fabsf(v.z), fabsf(v.w)));
    #pragma unroll
    for (int o = 16; o > 0; o >>= 1)
        m = fmaxf(m, __shfl_xor_sync(0xffffffffu, m, o));

    __shared__ float wmax[8];
    __shared__ float s_bcast;
    if ((threadIdx.x & 31) == 0) wmax[threadIdx.x >> 5] = m;
    __syncthreads();
    if (threadIdx.x == 0) {
        float mm = wmax[0];
        #pragma unroll
        for (int i = 1; i < 8; i++) mm = fmaxf(mm, wmax[i]);
        float s = mm / 127.0f;
        if (s == 0.0f) s = 1.0f;
        g_sA[row] = s;
        s_bcast = s;
    }
    __syncthreads();
    float s = s_bcast;
    char4 q;
    q.x = (char)(int)fminf(fmaxf(rintf(v.x / s), -127.0f), 127.0f);
    q.y = (char)(int)fminf(fmaxf(rintf(v.y / s), -127.0f), 127.0f);
    q.z = (char)(int)fminf(fmaxf(rintf(v.z / s), -127.0f), 127.0f);
    q.w = (char)(int)fminf(fmaxf(rintf(v.w / s), -127.0f), 127.0f);
    reinterpret_cast<char4*>(g_qA)[(size_t)row * 256 + threadIdx.x] = q;
}

// ---------------- GEMM kernel (int8 mma.sync) ----------------
// CTA 128x128, BK=128 (s8 -> 128B rows, SW128 XOR swizzle), 256 thr,
// 8 warps (2 M x 4 N), warp tile 64x32, 3-stage cp.async pipeline.
// grid = (N blocks, M blocks) so CTAs sharing an A tile are adjacent.

#define BM 128
#define BN 128
#define BK 128
#define NKB (K_DIM / BK)                // 8
#define STAGE_A 16384                   // 128 * 128 bytes
#define STAGE_B 16384
#define NSTAGE 3
#define SMEM_TOTAL (NSTAGE * (STAGE_A + STAGE_B))   // 98304

__global__ void __launch_bounds__(256, 2)
gemm_s8_kernel(float* __restrict__ out) {
    extern __shared__ __align__(1024) char smem[];
    uint32_t sbase = smem_u32(smem);
    int tid = threadIdx.x;
    int wid = tid >> 5;
    int lid = tid & 31;
    int warpm = wid & 1;        // 0..1 -> 64-row slab
    int warpn = wid >> 1;       // 0..3 -> 32-col slab
    int n0 = blockIdx.x * BN;   // N blocks on x (8)
    int m0 = blockIdx.y * BM;   // M blocks on y (256)

    uint32_t sA[NSTAGE], sB[NSTAGE];
    #pragma unroll
    for (int i = 0; i < NSTAGE; i++) {
        sA[i] = sbase + i * (STAGE_A + STAGE_B);
        sB[i] = sA[i] + STAGE_A;
    }

    const int8_t* gA = g_qA + (size_t)m0 * K_DIM;
    const int8_t* gB = g_qB + (size_t)n0 * K_DIM;

    // cp.async chunk mapping: chunk = tid + 256*i; r = chunk>>3, c = chunk&7
    // swizzled smem offset: r*128 + ((c ^ (r&7)) << 4)
    auto load_stage = [&](int st, int kb) {
        #pragma unroll
        for (int i = 0; i < 4; i++) {
            int chunk = tid + 256 * i;
            int r = chunk >> 3, c = chunk & 7;
            uint32_t off = (uint32_t)(r * 128 + ((c ^ (r & 7)) << 4));
            cp16(sA[st] + off, gA + (size_t)r * K_DIM + kb * BK + c * 16);
        }
        #pragma unroll
        for (int i = 0; i < 4; i++) {
            int chunk = tid + 256 * i;
            int r = chunk >> 3, c = chunk & 7;
            uint32_t off = (uint32_t)(r * 128 + ((c ^ (r & 7)) << 4));
            cp16(sB[st] + off, gB + (size_t)r * K_DIM + kb * BK + c * 16);
        }
        cp_commit();
    };

    // ldmatrix lane->matrix mapping for mma.m16n8k32 (verified R3, passed):
    // A: lanes 0-15 rows 0-15 chunk0; lanes 16-31 rows 0-15 chunk1.
    int lrowA = lid & 15;
    int halfA = lid >> 4;
    // B: lanes 0-7 n0-7/c0; 8-15 n0-7/c1; 16-23 n8-15/c0; 24-31 n8-15/c1.
    int lrowB = ((lid >> 4) << 3) + (lid & 7);
    int halfB = (lid >> 3) & 1;
    int phase = lid & 7;

    uint32_t aRow0 = (uint32_t)((warpm * 64 + lrowA) * 128);
    uint32_t bRow0 = (uint32_t)((warpn * 32 + lrowB) * 128);

    int32_t acc[4][4][4];
    #pragma unroll
    for (int mt = 0; mt < 4; mt++)
        #pragma unroll
        for (int nt = 0; nt < 4; nt++)
            #pragma unroll
            for (int i = 0; i < 4; i++) acc[mt][nt][i] = 0;

    load_stage(0, 0);
    load_stage(1, 1);
    load_stage(2, 2);

    for (int kb = 0; kb < NKB; kb++) {
        int st = kb % NSTAGE;
        cp_wait<NSTAGE - 1>();      // oldest outstanding group (stage kb) done
        __syncthreads();

        #pragma unroll
        for (int ks = 0; ks < 4; ks++) {
            uint32_t aChunk = (uint32_t)(((2 * ks + halfA) ^ phase) << 4);
            uint32_t bChunk = (uint32_t)(((2 * ks + halfB) ^ phase) << 4);
            uint32_t a[4][4], b[4][2];
            #pragma unroll
            for (int mt = 0; mt < 4; mt++) {
                uint32_t addr = sA[st] + aRow0 + (uint32_t)(mt * 16 * 128) + aChunk;
                ldsm_x4(a[mt][0], a[mt][1], a[mt][2], a[mt][3], addr);
            }
            #pragma unroll
            for (int np = 0; np < 2; np++) {
                uint32_t addr = sB[st] + bRow0 + (uint32_t)(np * 16 * 128) + bChunk;
                ldsm_x4(b[2 * np][0], b[2 * np][1], b[2 * np + 1][0], b[2 * np + 1][1], addr);
            }
            #pragma unroll
            for (int mt = 0; mt < 4; mt++)
                #pragma unroll
                for (int nt = 0; nt < 4; nt++)
                    mma_s8(acc[mt][nt], a[mt], b[nt]);
        }

        __syncthreads();
        if (kb + NSTAGE < NKB) load_stage(st, kb + NSTAGE);
    }

    // Epilogue: dequantize and store. Thread holds rows g,g+8 cols 2*tig,+1
    int g = lid >> 2, tig = lid & 3;
    #pragma unroll
    for (int mt = 0; mt < 4; mt++) {
        int mA = m0 + warpm * 64 + mt * 16 + g;
        float slA = g_sA[mA];
        float slB = g_sA[mA + 8];
        float* rowA = out + (size_t)mA * N_DIM + n0 + warpn * 32;
        float* rowB = rowA + 8 * N_DIM;
        #pragma unroll
        for (int nt = 0; nt < 4; nt++) {
            int n = nt * 8 + 2 * tig;
            float2 sr = *reinterpret_cast<const float2*>(&g_sB[n0 + warpn * 32 + n]);
            float2 vA, vB;
            vA.x = __int2float_rn(acc[mt][nt][0]) * slA * sr.x;
            vA.y = __int2float_rn(acc[mt][nt][1]) * slA * sr.y;
            vB.x = __int2float_rn(acc[mt][nt][2]) * slB * sr.x;
            vB.y = __int2float_rn(acc[mt][nt][3]) * slB * sr.y;
            *reinterpret_cast<float2*>(rowA + n) = vA;
            *reinterpret_cast<float2*>(rowB + n) = vB;
        }
    }
}

// ---------------- Launch ----------------
extern "C" void kernel_launch(void* const* d_in, const int* in_sizes, int n_in,
                              void* d_out, int out_size) {
    const float* lhs = (const float*)d_in[0];   // [32768, 1024] f32
    const float* rhs = (const float*)d_in[1];   // [1024, 1024] f32
    float* out = (float*)d_out;                 // [32768, 1024] f32

    int M = in_sizes[0] / K_DIM;                // 32768

    cudaFuncSetAttribute(gemm_s8_kernel,
                         cudaFuncAttributeMaxDynamicSharedMemorySize, SMEM_TOTAL);

    rhs_pmax_kernel<<<dim3(8, 16), 256>>>(rhs);
    quant_rhs2_kernel<<<dim3(8, 16), 256>>>(rhs);
    quant_lhs_kernel<<<M, 256>>>(lhs);

    dim3 grid(N_DIM / BN, M / BM);              // (8, 256)
    gemm_s8_kernel<<<grid, 256, SMEM_TOTAL>>>(out);
}